// round 2
// baseline (speedup 1.0000x reference)
#include <cuda_runtime.h>
#include <math.h>

// Problem constants
#define BB   4
#define NQ   1024     // N
#define MM   512      // M (context len)
#define DD   512      // D
#define PP   256      // P
#define HH   8
#define DH   64
#define LL   6
#define FFI  2048
#define RR   (BB*NQ)        // 4096 rows of x
#define CR   (BB*MM)        // 2048 rows of context
#define SLD  1028           // scores row stride (>= 1025, mult of 4)

// ---------------- scratch (static device globals; no allocation) ----------
__device__ float g_x   [RR*DD];
__device__ float g_xn  [RR*DD];
__device__ float g_ctxn[CR*PP];
__device__ float g_q   [RR*DD];
__device__ float g_kv  [RR*128];
__device__ float g_k   [BB*(NQ+1)*DH];
__device__ float g_v   [BB*(NQ+1)*DH];
__device__ float g_att [RR*DD];
__device__ float g_hh  [(size_t)RR*FFI];
__device__ float g_hg  [(size_t)RR*2*FFI];
__device__ float g_sc  [(size_t)BB*HH*NQ*SLD];

// ---------------- reductions (blockDim == 256) -----------------------------
__device__ __forceinline__ float warpSum(float v){
    #pragma unroll
    for (int o=16;o;o>>=1) v += __shfl_xor_sync(0xffffffffu, v, o);
    return v;
}
__device__ __forceinline__ float warpMax(float v){
    #pragma unroll
    for (int o=16;o;o>>=1) v = fmaxf(v, __shfl_xor_sync(0xffffffffu, v, o));
    return v;
}
__device__ float blockSum(float v){
    __shared__ float sh[8];
    int lane = threadIdx.x & 31, w = threadIdx.x >> 5;
    v = warpSum(v);
    if (lane == 0) sh[w] = v;
    __syncthreads();
    v = (threadIdx.x < 8) ? sh[threadIdx.x] : 0.f;
    v = warpSum(v);
    if (threadIdx.x == 0) sh[0] = v;
    __syncthreads();
    float r = sh[0];
    __syncthreads();
    return r;
}
__device__ float blockMax(float v){
    __shared__ float sh[8];
    int lane = threadIdx.x & 31, w = threadIdx.x >> 5;
    v = warpMax(v);
    if (lane == 0) sh[w] = v;
    __syncthreads();
    v = (threadIdx.x < 8) ? sh[threadIdx.x] : -3.4e38f;
    v = warpMax(v);
    if (threadIdx.x == 0) sh[0] = v;
    __syncthreads();
    float r = sh[0];
    __syncthreads();
    return r;
}

// ---------------- elementwise kernels --------------------------------------
__global__ void copy_kernel(const float* __restrict__ in, float* __restrict__ out, int n){
    for (int i = blockIdx.x*blockDim.x + threadIdx.x; i < n; i += gridDim.x*blockDim.x)
        out[i] = in[i];
}
__global__ void add_kernel(float* __restrict__ x, const float* __restrict__ y, int n){
    for (int i = blockIdx.x*blockDim.x + threadIdx.x; i < n; i += gridDim.x*blockDim.x)
        x[i] += y[i];
}
__global__ void glu_kernel(const float* __restrict__ hg, float* __restrict__ out){
    // hg: [RR, 2*FFI]; out: [RR, FFI]; out = h * silu(gate)
    long total = (long)RR * FFI;
    for (long i = blockIdx.x*(long)blockDim.x + threadIdx.x; i < total; i += gridDim.x*(long)blockDim.x){
        long r = i / FFI; int c = (int)(i - r*FFI);
        float h = hg[r*(2*FFI) + c];
        float g = hg[r*(2*FFI) + FFI + c];
        out[i] = h * (g / (1.f + expf(-g)));
    }
}

// ---------------- layernorm family (1 block / row, 256 thr, cols<=512) -----
__global__ __launch_bounds__(256) void ln_kernel(const float* __restrict__ in,
                                                 const float* __restrict__ g,
                                                 float* __restrict__ out, int cols){
    long ro = (long)blockIdx.x * cols;
    int t = threadIdx.x;
    float v0 = (t       < cols) ? in[ro + t]       : 0.f;
    float v1 = (t + 256 < cols) ? in[ro + t + 256] : 0.f;
    float mu = blockSum(v0 + v1) / (float)cols;
    float d0 = (t       < cols) ? v0 - mu : 0.f;
    float d1 = (t + 256 < cols) ? v1 - mu : 0.f;
    float var = blockSum(d0*d0 + d1*d1) / (float)cols;
    float inv = 1.f / sqrtf(var + 1e-5f);
    if (t       < cols) out[ro + t]       = d0 * inv * g[t];
    if (t + 256 < cols) out[ro + t + 256] = d1 * inv * g[t + 256];
}
__global__ __launch_bounds__(256) void ln_res_kernel(const float* __restrict__ in,
                                                     const float* __restrict__ g,
                                                     float* __restrict__ x, int cols){
    long ro = (long)blockIdx.x * cols;
    int t = threadIdx.x;
    float v0 = (t       < cols) ? in[ro + t]       : 0.f;
    float v1 = (t + 256 < cols) ? in[ro + t + 256] : 0.f;
    float mu = blockSum(v0 + v1) / (float)cols;
    float d0 = (t       < cols) ? v0 - mu : 0.f;
    float d1 = (t + 256 < cols) ? v1 - mu : 0.f;
    float var = blockSum(d0*d0 + d1*d1) / (float)cols;
    float inv = 1.f / sqrtf(var + 1e-5f);
    if (t       < cols) x[ro + t]       += d0 * inv * g[t];
    if (t + 256 < cols) x[ro + t + 256] += d1 * inv * g[t + 256];
}
__global__ __launch_bounds__(256) void final_ln_kernel(const float* __restrict__ in,
                                                       const float* __restrict__ g,
                                                       float* __restrict__ out, int cols){
    long ro = (long)blockIdx.x * cols;
    int t = threadIdx.x;
    float v0 = (t       < cols) ? in[ro + t]       : 0.f;
    float v1 = (t + 256 < cols) ? in[ro + t + 256] : 0.f;
    float m0 = (t       < cols) ? v0 : -3.4e38f;
    float m1 = (t + 256 < cols) ? v1 : -3.4e38f;
    float mx = blockMax(fmaxf(m0, m1));
    v0 /= mx; v1 /= mx;
    float s0 = (t       < cols) ? v0 : 0.f;
    float s1 = (t + 256 < cols) ? v1 : 0.f;
    float mu = blockSum(s0 + s1) / (float)cols;
    float d0 = (t       < cols) ? v0 - mu : 0.f;
    float d1 = (t + 256 < cols) ? v1 - mu : 0.f;
    float var = blockSum(d0*d0 + d1*d1) / (float)cols;
    float inv = 1.f / sqrtf(var + 1e-5f);
    if (t       < cols) out[ro + t]       = d0 * inv * g[t];
    if (t + 256 < cols) out[ro + t + 256] = d1 * inv * g[t + 256];
}

// ---------------- rotary / prep --------------------------------------------
__device__ __forceinline__ float inv_freq(int m){
    // 1 / 10000^(m/16)
    return powf(10000.f, -(float)m * (1.f/16.f));
}
// q: [RR, 512]; scale by DH^-0.5; rotary on first 32 dims of each head
__global__ __launch_bounds__(256) void qprep_kernel(float* __restrict__ q, int n, int use_rot){
    int idx = blockIdx.x * 256 + threadIdx.x;
    int row = idx >> 8;           // 256 work-items per row (8 heads * 32)
    int r   = idx & 255;
    int h = r >> 5, t = r & 31;
    float* p = q + (long)row * DD + h * DH;
    const float sc = 0.125f;      // 64^-0.5
    if (t < 16){
        float a = p[t] * sc, b = p[t+16] * sc;
        if (use_rot){
            float f = (float)(row % n) * inv_freq(t);
            float cf = cosf(f), sf = sinf(f);
            p[t]    = a*cf - b*sf;
            p[t+16] = a*sf + b*cf;
        } else { p[t] = a; p[t+16] = b; }
    } else {
        p[t+16] *= sc;
        p[t+32] *= sc;
    }
}
// kv: [B*nk, 128] -> k/v buffers [B, nk+1, 64] with null at j=0; rotary on k
__global__ __launch_bounds__(64) void kvprep_kernel(const float* __restrict__ kv,
                                                    const float* __restrict__ null_kv,
                                                    float* __restrict__ kbuf, float* __restrict__ vbuf,
                                                    int nk, int use_rot){
    int rblk = blockIdx.x;
    int d = threadIdx.x;
    int nkv = nk + 1;
    int b = rblk / nkv, j = rblk % nkv;
    long doff = ((long)b * nkv + j) * DH + d;
    if (j == 0){
        kbuf[doff] = null_kv[d];
        vbuf[doff] = null_kv[DH + d];
        return;
    }
    int i = j - 1;
    const float* src = kv + ((long)b * nk + i) * 128;
    float kval = src[d];
    float vval = src[DH + d];
    if (use_rot && d < 32){
        int m = d & 15;
        float f = (float)i * inv_freq(m);
        float cf = cosf(f), sf = sinf(f);
        if (d < 16) kval = kval*cf - src[d+16]*sf;
        else        kval = kval*cf + src[d-16]*sf;
    }
    kbuf[doff] = kval;
    vbuf[doff] = vval;
}

// ---------------- generic SGEMM: C = A(MxK) @ B(KxN), all mult of tile -----
#define GBM 128
#define GBN 128
#define GBK 16
__global__ __launch_bounds__(256) void sgemm128(const float* __restrict__ A,
                                                const float* __restrict__ Bm,
                                                float* __restrict__ C,
                                                int M, int N, int K){
    __shared__ float As[GBK][GBM + 4];
    __shared__ float Bs[GBK][GBN + 4];
    int t  = threadIdx.x;
    int tx = t & 15, ty = t >> 4;
    int rowBase = blockIdx.y * GBM;
    int colBase = blockIdx.x * GBN;
    float acc[8][8];
    #pragma unroll
    for (int i=0;i<8;i++)
        #pragma unroll
        for (int j=0;j<8;j++) acc[i][j] = 0.f;

    for (int k0 = 0; k0 < K; k0 += GBK){
        #pragma unroll
        for (int i=0;i<2;i++){
            int fi = t + i*256;
            int ar = fi >> 2, ac4 = fi & 3;
            float4 va = *(const float4*)(A + (long)(rowBase + ar)*K + k0 + ac4*4);
            As[ac4*4+0][ar] = va.x; As[ac4*4+1][ar] = va.y;
            As[ac4*4+2][ar] = va.z; As[ac4*4+3][ar] = va.w;
            int br = fi >> 5, bc4 = fi & 31;
            *(float4*)&Bs[br][bc4*4] =
                *(const float4*)(Bm + (long)(k0 + br)*N + colBase + bc4*4);
        }
        __syncthreads();
        #pragma unroll
        for (int k=0;k<GBK;k++){
            float a[8], b[8];
            *(float4*)&a[0] = *(const float4*)&As[k][ty*8];
            *(float4*)&a[4] = *(const float4*)&As[k][ty*8+4];
            *(float4*)&b[0] = *(const float4*)&Bs[k][tx*8];
            *(float4*)&b[4] = *(const float4*)&Bs[k][tx*8+4];
            #pragma unroll
            for (int i=0;i<8;i++)
                #pragma unroll
                for (int j=0;j<8;j++) acc[i][j] = fmaf(a[i], b[j], acc[i][j]);
        }
        __syncthreads();
    }
    #pragma unroll
    for (int i=0;i<8;i++){
        float* cr = C + (long)(rowBase + ty*8 + i)*N + colBase + tx*8;
        *(float4*)cr       = *(float4*)&acc[i][0];
        *(float4*)(cr + 4) = *(float4*)&acc[i][4];
    }
}

// ---------------- attention: scores = q@k^T (+bias, mask) ------------------
__global__ __launch_bounds__(256) void scores_kernel(const float* __restrict__ q,
                                                     const float* __restrict__ kbuf,
                                                     const float* __restrict__ rel_emb,
                                                     float* __restrict__ scores,
                                                     int nq, int nkv, int cb){
    __shared__ float Qs[64][64];  // [d][i]
    __shared__ float Ks[64][64];  // [d][j]
    int t  = threadIdx.x;
    int bh = blockIdx.z, b = bh >> 3, h = bh & 7;
    int i0 = blockIdx.y * 64, j0 = blockIdx.x * 64;
    #pragma unroll
    for (int n=0;n<4;n++){
        int fi = t + n*256;
        int r = fi >> 4, c4 = fi & 15;
        float4 v = *(const float4*)(q + ((long)(b*nq + i0 + r))*DD + h*DH + c4*4);
        Qs[c4*4+0][r]=v.x; Qs[c4*4+1][r]=v.y; Qs[c4*4+2][r]=v.z; Qs[c4*4+3][r]=v.w;
        int j = j0 + r;
        float4 w = make_float4(0.f,0.f,0.f,0.f);
        if (j < nkv) w = *(const float4*)(kbuf + ((long)b*nkv + j)*DH + c4*4);
        Ks[c4*4+0][r]=w.x; Ks[c4*4+1][r]=w.y; Ks[c4*4+2][r]=w.z; Ks[c4*4+3][r]=w.w;
    }
    __syncthreads();
    int tx = t & 15, ty = t >> 4;
    float acc[4][4];
    #pragma unroll
    for (int i=0;i<4;i++)
        #pragma unroll
        for (int j=0;j<4;j++) acc[i][j]=0.f;
    #pragma unroll 4
    for (int d=0; d<64; d++){
        float a[4], bb[4];
        *(float4*)a  = *(const float4*)&Qs[d][ty*4];
        *(float4*)bb = *(const float4*)&Ks[d][tx*4];
        #pragma unroll
        for (int i=0;i<4;i++)
            #pragma unroll
            for (int j=0;j<4;j++) acc[i][j] = fmaf(a[i], bb[j], acc[i][j]);
    }
    #pragma unroll
    for (int ii=0;ii<4;ii++){
        int i = i0 + ty*4 + ii;
        #pragma unroll
        for (int jj=0;jj<4;jj++){
            int j = j0 + tx*4 + jj;
            if (j >= nkv) continue;
            float s = acc[ii][jj];
            if (cb){
                int nn = i - j; if (nn < 0) nn = 0;
                int bucket;
                if (nn < 16) bucket = nn;
                else {
                    int large = 16 + (int)(logf((float)nn * 0.0625f) * (16.0f / 2.0794415416798357f));
                    bucket = large < 31 ? large : 31;
                }
                s += rel_emb[bucket*HH + h];
                if (j > i + 1) s = -1e30f;   // causal mask (j <= i+1 allowed)
            }
            scores[((long)bh*nq + i)*SLD + j] = s;
        }
    }
}

// ---------------- softmax over rows of scores -------------------------------
__global__ __launch_bounds__(256) void softmax_kernel(float* __restrict__ scores, int nkv){
    long off = (long)blockIdx.x * SLD;
    int t = threadIdx.x;
    float v[5];
    int cnt = 0;
    float mx = -3.4e38f;
    for (int j = t; j < nkv; j += 256){ v[cnt] = scores[off + j]; mx = fmaxf(mx, v[cnt]); cnt++; }
    mx = blockMax(mx);
    float s = 0.f;
    for (int c=0;c<cnt;c++){ v[c] = expf(v[c] - mx); s += v[c]; }
    s = blockSum(s);
    float inv = 1.f / s;
    cnt = 0;
    for (int j = t; j < nkv; j += 256) scores[off + j] = v[cnt++] * inv;
}

// ---------------- out = attn @ v, scattered into [B*N, 512] ----------------
__global__ __launch_bounds__(256) void av_kernel(const float* __restrict__ scores,
                                                 const float* __restrict__ vbuf,
                                                 float* __restrict__ out,
                                                 int nq, int nkv){
    __shared__ float Ps[16][64];  // [k][i]
    __shared__ float Vs[16][64];  // [k][d]
    int t  = threadIdx.x;
    int bh = blockIdx.z, b = bh >> 3, h = bh & 7;
    int i0 = blockIdx.y * 64;
    int tx = t & 15, ty = t >> 4;
    const float* srow = scores + (long)bh * nq * SLD;
    float acc[4][4];
    #pragma unroll
    for (int i=0;i<4;i++)
        #pragma unroll
        for (int j=0;j<4;j++) acc[i][j]=0.f;
    for (int k0 = 0; k0 < nkv; k0 += 16){
        int pr = t >> 2, pc = (t & 3)*4;
        #pragma unroll
        for (int e=0;e<4;e++){
            int kk = k0 + pc + e;
            Ps[pc+e][pr] = (kk < nkv) ? srow[(long)(i0 + pr)*SLD + kk] : 0.f;
        }
        int vr = t >> 4, vc4 = t & 15;
        int kk2 = k0 + vr;
        float4 w = make_float4(0.f,0.f,0.f,0.f);
        if (kk2 < nkv) w = *(const float4*)(vbuf + ((long)b*nkv + kk2)*DH + vc4*4);
        *(float4*)&Vs[vr][vc4*4] = w;
        __syncthreads();
        #pragma unroll
        for (int kk=0;kk<16;kk++){
            float a[4], bb[4];
            *(float4*)a  = *(const float4*)&Ps[kk][ty*4];
            *(float4*)bb = *(const float4*)&Vs[kk][tx*4];
            #pragma unroll
            for (int i=0;i<4;i++)
                #pragma unroll
                for (int j=0;j<4;j++) acc[i][j] = fmaf(a[i], bb[j], acc[i][j]);
        }
        __syncthreads();
    }
    #pragma unroll
    for (int ii=0;ii<4;ii++)
        #pragma unroll
        for (int jj=0;jj<4;jj++)
            out[((long)(b*nq + i0 + ty*4 + ii))*DD + h*DH + tx*4 + jj] = acc[ii][jj];
}

// ---------------- orchestration --------------------------------------------
extern "C" void kernel_launch(void* const* d_in, const int* in_sizes, int n_in,
                              void* d_out, int out_size){
    const float* x_in    = (const float*)d_in[0];
    const float* ctx     = (const float*)d_in[1];
    const float* rel_emb = (const float*)d_in[2];
    const float* sa_ng   = (const float*)d_in[3];
    const float* sa_wq   = (const float*)d_in[4];
    const float* sa_wkv  = (const float*)d_in[5];
    const float* sa_null = (const float*)d_in[6];
    const float* sa_wo   = (const float*)d_in[7];
    const float* sa_og   = (const float*)d_in[8];
    const float* ca_ng   = (const float*)d_in[9];
    const float* ca_cg   = (const float*)d_in[10];
    const float* ca_wq   = (const float*)d_in[11];
    const float* ca_wkv  = (const float*)d_in[12];
    const float* ca_null = (const float*)d_in[13];
    const float* ca_wo   = (const float*)d_in[14];
    const float* ca_og   = (const float*)d_in[15];
    const float* ff_ng   = (const float*)d_in[16];
    const float* ff_w1   = (const float*)d_in[17];
    const float* ff_w2   = (const float*)d_in[18];
    const float* normg   = (const float*)d_in[19];
    float* out = (float*)d_out;

    float *X,*XN,*CTXN,*Q,*KV,*K_,*V_,*ATT,*HHp,*HG,*SC;
    cudaGetSymbolAddress((void**)&X,    g_x);
    cudaGetSymbolAddress((void**)&XN,   g_xn);
    cudaGetSymbolAddress((void**)&CTXN, g_ctxn);
    cudaGetSymbolAddress((void**)&Q,    g_q);
    cudaGetSymbolAddress((void**)&KV,   g_kv);
    cudaGetSymbolAddress((void**)&K_,   g_k);
    cudaGetSymbolAddress((void**)&V_,   g_v);
    cudaGetSymbolAddress((void**)&ATT,  g_att);
    cudaGetSymbolAddress((void**)&HHp,  g_hh);
    cudaGetSymbolAddress((void**)&HG,   g_hg);
    cudaGetSymbolAddress((void**)&SC,   g_sc);

    copy_kernel<<<512, 256>>>(x_in, X, RR*DD);

    for (int l = 0; l < LL; l++){
        // ---------------- self-attention ----------------
        ln_kernel<<<RR, 256>>>(X, sa_ng + l*DD, XN, DD);
        sgemm128<<<dim3(DD/128, RR/128), 256>>>(XN, sa_wq + (size_t)l*DD*DD, Q, RR, DD, DD);
        sgemm128<<<dim3(1, RR/128), 256>>>(XN, sa_wkv + (size_t)l*DD*128, KV, RR, 128, DD);
        qprep_kernel<<<RR, 256>>>(Q, NQ, 1);
        kvprep_kernel<<<BB*(NQ+1), 64>>>(KV, sa_null + l*128, K_, V_, NQ, 1);
        scores_kernel<<<dim3((NQ+1+63)/64, NQ/64, BB*HH), 256>>>(Q, K_, rel_emb, SC, NQ, NQ+1, 1);
        softmax_kernel<<<BB*HH*NQ, 256>>>(SC, NQ+1);
        av_kernel<<<dim3(1, NQ/64, BB*HH), 256>>>(SC, V_, ATT, NQ, NQ+1);
        sgemm128<<<dim3(DD/128, RR/128), 256>>>(ATT, sa_wo + (size_t)l*DD*DD, Q, RR, DD, DD);
        ln_res_kernel<<<RR, 256>>>(Q, sa_og + l*DD, X, DD);

        // ---------------- cross-attention ----------------
        ln_kernel<<<RR, 256>>>(X, ca_ng + l*DD, XN, DD);
        ln_kernel<<<CR, 256>>>(ctx, ca_cg + l*PP, CTXN, PP);
        sgemm128<<<dim3(DD/128, RR/128), 256>>>(XN, ca_wq + (size_t)l*DD*DD, Q, RR, DD, DD);
        sgemm128<<<dim3(1, CR/128), 256>>>(CTXN, ca_wkv + (size_t)l*PP*128, KV, CR, 128, PP);
        qprep_kernel<<<RR, 256>>>(Q, NQ, 0);
        kvprep_kernel<<<BB*(MM+1), 64>>>(KV, ca_null + l*128, K_, V_, MM, 0);
        scores_kernel<<<dim3((MM+1+63)/64, NQ/64, BB*HH), 256>>>(Q, K_, rel_emb, SC, NQ, MM+1, 0);
        softmax_kernel<<<BB*HH*NQ, 256>>>(SC, MM+1);
        av_kernel<<<dim3(1, NQ/64, BB*HH), 256>>>(SC, V_, ATT, NQ, MM+1);
        sgemm128<<<dim3(DD/128, RR/128), 256>>>(ATT, ca_wo + (size_t)l*DD*DD, Q, RR, DD, DD);
        ln_res_kernel<<<RR, 256>>>(Q, ca_og + l*DD, X, DD);

        // ---------------- feed-forward (SwiGLU) ----------------
        ln_kernel<<<RR, 256>>>(X, ff_ng + l*DD, XN, DD);
        sgemm128<<<dim3((2*FFI)/128, RR/128), 256>>>(XN, ff_w1 + (size_t)l*DD*2*FFI, HG, RR, 2*FFI, DD);
        glu_kernel<<<2048, 256>>>(HG, HHp);
        sgemm128<<<dim3(DD/128, RR/128), 256>>>(HHp, ff_w2 + (size_t)l*FFI*DD, Q, RR, DD, FFI);
        add_kernel<<<1024, 256>>>(X, Q, RR*DD);
    }

    final_ln_kernel<<<RR, 256>>>(X, normg, out, DD);
}